// round 6
// baseline (speedup 1.0000x reference)
#include <cuda_runtime.h>
#include <cuda_bf16.h>
#include <cuda_fp16.h>
#include <cstdint>
#include <cstddef>

#define NN 100000
#define NE 1600000
#define SCAN_B 512
#define SCAN_NB ((NN + SCAN_B - 1) / SCAN_B)   // 196
#define NSM 152

// ---------------- scratch (static device globals; no allocs allowed) ----------------
__device__ int   g_degi[NN];
__device__ float g_dinv[NN];
__device__ int   g_src[NE];
__device__ int   g_dst[NE];
__device__ int   g_csr[NE];
__device__ int   g_rowptr[NN + 1];
__device__ int   g_cursor[NN];
__device__ int   g_bsum[256];
__device__ __align__(16) float  g_agg1[(size_t)NN * 40];
__device__ __align__(16) float  g_h1[(size_t)NN * 64];
__device__ __align__(16) __half g_xh[(size_t)NN * 40];
__device__ __align__(16) __half g_h1h[(size_t)NN * 64];
__device__ __align__(16) float  g_agg2[(size_t)NN * 64];
__device__ __align__(16) float  g_h2[(size_t)NN * 128];
__device__ __align__(16) float  g_z[(size_t)NN * 4];

// ==================== CSR build ====================
__global__ void k_zero0() {
    int i = blockIdx.x * blockDim.x + threadIdx.x;
    if (i < NN) g_degi[i] = 0;
}

__global__ void k_edges(const int* __restrict__ ei32) {
    bool is64 = true;
#pragma unroll
    for (int q = 1; q < 16; q += 2) is64 = is64 && (ei32[q] == 0);
    int e = blockIdx.x * blockDim.x + threadIdx.x;
    if (e >= NE) return;
    int s, d;
    if (is64) { s = ei32[2 * e];  d = ei32[2 * (NE + e)]; }
    else      { s = ei32[e];      d = ei32[NE + e]; }
    g_src[e] = s;
    g_dst[e] = d;
    atomicAdd(&g_degi[d], 1);
}

// block-local inclusive scan + per-block sum + dinv
__global__ void k_scan1() {
    __shared__ int sh[SCAN_B];
    int i = blockIdx.x * SCAN_B + threadIdx.x;
    int v = (i < NN) ? g_degi[i] : 0;
    sh[threadIdx.x] = v;
    __syncthreads();
    for (int off = 1; off < SCAN_B; off <<= 1) {
        int t = (threadIdx.x >= off) ? sh[threadIdx.x - off] : 0;
        __syncthreads();
        sh[threadIdx.x] += t;
        __syncthreads();
    }
    if (i < NN) {
        g_rowptr[i] = sh[threadIdx.x] - v;  // block-local exclusive
        g_dinv[i] = (v > 0) ? (1.f / (float)v) : 0.f;
    }
    if (threadIdx.x == SCAN_B - 1) g_bsum[blockIdx.x] = sh[threadIdx.x];
}

// finalize rowptr/cursor; nb = i/SCAN_B is CONSTANT per 256-thread block ->
// compute the bsum prefix with a parallel block reduction (was: serial loop, 9us)
__global__ void k_scanf() {
    __shared__ int ssum[8];
    int tid = threadIdx.x;
    int nb = (blockIdx.x * 256) / SCAN_B;
    int part = 0;
    for (int b = tid; b < nb; b += 256) part += g_bsum[b];
#pragma unroll
    for (int o = 16; o; o >>= 1) part += __shfl_down_sync(0xFFFFFFFFu, part, o);
    if ((tid & 31) == 0) ssum[tid >> 5] = part;
    __syncthreads();
    int off = ssum[0] + ssum[1] + ssum[2] + ssum[3]
            + ssum[4] + ssum[5] + ssum[6] + ssum[7];
    int i = blockIdx.x * 256 + tid;
    if (i >= NN) return;
    int rp = g_rowptr[i] + off;
    g_rowptr[i] = rp;
    g_cursor[i] = rp;
    if (i == 0) g_rowptr[NN] = NE;
}

__global__ void k_fill() {
    int e = blockIdx.x * blockDim.x + threadIdx.x;
    if (e >= NE) return;
    int pos = atomicAdd(&g_cursor[g_dst[e]], 1);
    g_csr[pos] = g_src[e];
}

// ==================== x -> fp16 mirror ====================
__global__ void k_xhalf(const float* __restrict__ x) {
    int t = blockIdx.x * blockDim.x + threadIdx.x;  // one float4 -> 4 halves
    if (t >= NN * 10) return;
    float4 v = reinterpret_cast<const float4*>(x)[t];
    __half2 a = __floats2half2_rn(v.x, v.y);
    __half2 b = __floats2half2_rn(v.z, v.w);
    reinterpret_cast<uint2*>(g_xh)[t] =
        make_uint2(*reinterpret_cast<uint32_t*>(&a), *reinterpret_cast<uint32_t*>(&b));
}

// ==================== CSR gather (fp16 payload): agg[n] = dinv[n]*sum feat[nbrs] ====================
// FC chunks of 4 halves per row; accumulate fp32; unroll x4 for MLP
template <int FC>
__global__ void k_gather_h(const __half* __restrict__ feat, float* __restrict__ agg) {
    int t = blockIdx.x * blockDim.x + threadIdx.x;
    if (t >= NN * FC) return;
    int n = t / FC;
    int c = t - n * FC;
    int beg = g_rowptr[n], end = g_rowptr[n + 1];
    const uint2* f = reinterpret_cast<const uint2*>(feat);
    float4 a0 = make_float4(0.f, 0.f, 0.f, 0.f), a1 = a0, a2 = a0, a3 = a0;
    int i = beg;
    for (; i + 4 <= end; i += 4) {
        int s0 = g_csr[i], s1 = g_csr[i + 1], s2 = g_csr[i + 2], s3 = g_csr[i + 3];
        uint2 u0 = f[(size_t)s0 * FC + c];
        uint2 u1 = f[(size_t)s1 * FC + c];
        uint2 u2 = f[(size_t)s2 * FC + c];
        uint2 u3 = f[(size_t)s3 * FC + c];
        float2 p, q;
        p = __half22float2(*reinterpret_cast<__half2*>(&u0.x));
        q = __half22float2(*reinterpret_cast<__half2*>(&u0.y));
        a0.x += p.x; a0.y += p.y; a0.z += q.x; a0.w += q.y;
        p = __half22float2(*reinterpret_cast<__half2*>(&u1.x));
        q = __half22float2(*reinterpret_cast<__half2*>(&u1.y));
        a1.x += p.x; a1.y += p.y; a1.z += q.x; a1.w += q.y;
        p = __half22float2(*reinterpret_cast<__half2*>(&u2.x));
        q = __half22float2(*reinterpret_cast<__half2*>(&u2.y));
        a2.x += p.x; a2.y += p.y; a2.z += q.x; a2.w += q.y;
        p = __half22float2(*reinterpret_cast<__half2*>(&u3.x));
        q = __half22float2(*reinterpret_cast<__half2*>(&u3.y));
        a3.x += p.x; a3.y += p.y; a3.z += q.x; a3.w += q.y;
    }
    for (; i < end; i++) {
        uint2 u = f[(size_t)g_csr[i] * FC + c];
        float2 p = __half22float2(*reinterpret_cast<__half2*>(&u.x));
        float2 q = __half22float2(*reinterpret_cast<__half2*>(&u.y));
        a0.x += p.x; a0.y += p.y; a0.z += q.x; a0.w += q.y;
    }
    float di = g_dinv[n];
    float4 acc;
    acc.x = ((a0.x + a1.x) + (a2.x + a3.x)) * di;
    acc.y = ((a0.y + a1.y) + (a2.y + a3.y)) * di;
    acc.z = ((a0.z + a1.z) + (a2.z + a3.z)) * di;
    acc.w = ((a0.w + a1.w) + (a2.w + a3.w)) * di;
    reinterpret_cast<float4*>(agg)[t] = acc;
}

// ==================== HMMA helpers ====================
__device__ __forceinline__ void mma_bf16(float* c, uint32_t a0, uint32_t a1,
                                         uint32_t a2, uint32_t a3,
                                         uint32_t b0, uint32_t b1) {
    asm volatile(
        "mma.sync.aligned.m16n8k16.row.col.f32.bf16.bf16.f32 "
        "{%0,%1,%2,%3}, {%4,%5,%6,%7}, {%8,%9}, {%0,%1,%2,%3};"
        : "+f"(c[0]), "+f"(c[1]), "+f"(c[2]), "+f"(c[3])
        : "r"(a0), "r"(a1), "r"(a2), "r"(a3), "r"(b0), "r"(b1));
}

__device__ __forceinline__ uint32_t pack_bf(float a, float b) {
    __nv_bfloat162 t = __floats2bfloat162_rn(a, b);
    return *reinterpret_cast<uint32_t*>(&t);
}

__device__ __forceinline__ void store_hilo(char* pHi, char* pLo, float4 v) {
    float hx = __bfloat162float(__float2bfloat16_rn(v.x));
    float hy = __bfloat162float(__float2bfloat16_rn(v.y));
    float hz = __bfloat162float(__float2bfloat16_rn(v.z));
    float hw = __bfloat162float(__float2bfloat16_rn(v.w));
    *reinterpret_cast<uint2*>(pHi) = make_uint2(pack_bf(hx, hy), pack_bf(hz, hw));
    *reinterpret_cast<uint2*>(pLo) =
        make_uint2(pack_bf(v.x - hx, v.y - hy), pack_bf(v.z - hz, v.w - hw));
}

// ==================== fused SAGE layer via mma.sync (bf16 hi/lo split) ====================
// out[:, coloff:coloff+NOUTB] = act([agg|in] @ [Wl;Wr]^T + b); optional fp16 mirror write.
template <int K, int NOUTB, bool RELU, bool WRITEH>
__global__ void __launch_bounds__(256) k_layer_mma(
        const float* __restrict__ in, const float* __restrict__ agg,
        const float* __restrict__ Wl, const float* __restrict__ bias,
        const float* __restrict__ Wr, float* __restrict__ out,
        __half* __restrict__ outh, int NOUT) {
    constexpr int Kc = 2 * K;
    constexpr int KSTEPS = Kc / 16;
    constexpr int K4 = Kc / 4;
    constexpr int SA = Kc + 8;           // +16B row pad: conflict-free frag loads
    constexpr int SAB = SA * 2;
    constexpr int NT = (NOUTB / 2) / 8;
    constexpr int NTILES = (NN + 127) / 128;
    constexpr int OFF_AH = 512;
    constexpr int OFF_AL = OFF_AH + 128 * SAB;
    constexpr int OFF_BH = OFF_AL + 128 * SAB;
    constexpr int OFF_BL = OFF_BH + NOUTB * SAB;

    extern __shared__ char smem[];
    float* sbias = reinterpret_cast<float*>(smem);
    char* sAh = smem + OFF_AH;
    char* sAl = smem + OFF_AL;
    char* sBh = smem + OFF_BH;
    char* sBl = smem + OFF_BL;

    int tid = threadIdx.x;
    int wid = tid >> 5, lane = tid & 31;
    int g = lane >> 2, tg = lane & 3;
    int mwarp = (wid & 3) * 32;
    int nwarp = (wid >> 2) * (NOUTB / 2);
    int coloff = blockIdx.y * NOUTB;

    if (tid < NOUTB) sbias[tid] = bias[coloff + tid];
    for (int idx = tid; idx < NOUTB * K4; idx += 256) {
        int row = idx / K4, k4 = idx - row * K4;
        int k = k4 * 4;
        int grow = coloff + row;
        float4 v = (k < K)
            ? *reinterpret_cast<const float4*>(Wl + (size_t)grow * K + k)
            : *reinterpret_cast<const float4*>(Wr + (size_t)grow * K + (k - K));
        store_hilo(sBh + row * SAB + k * 2, sBl + row * SAB + k * 2, v);
    }
    __syncthreads();

    for (int tile = blockIdx.x; tile < NTILES; tile += gridDim.x) {
        int r0 = tile * 128;
        for (int idx = tid; idx < 128 * K4; idx += 256) {
            int row = idx / K4, k4 = idx - row * K4;
            int k = k4 * 4;
            int gr = r0 + row;
            float4 v = make_float4(0.f, 0.f, 0.f, 0.f);
            if (gr < NN) {
                v = (k < K)
                    ? *reinterpret_cast<const float4*>(agg + (size_t)gr * K + k)
                    : *reinterpret_cast<const float4*>(in + (size_t)gr * K + (k - K));
            }
            store_hilo(sAh + row * SAB + k * 2, sAl + row * SAB + k * 2, v);
        }
        __syncthreads();

        float C[2][NT][4];
#pragma unroll
        for (int mt = 0; mt < 2; mt++)
#pragma unroll
            for (int nt = 0; nt < NT; nt++)
#pragma unroll
                for (int q = 0; q < 4; q++) C[mt][nt][q] = 0.f;

#pragma unroll
        for (int ks = 0; ks < KSTEPS; ks++) {
            int kb = ks * 16;
            uint32_t Ah[2][4], Al[2][4];
#pragma unroll
            for (int mt = 0; mt < 2; mt++) {
                const char* pa = sAh + (mwarp + mt * 16 + g) * SAB + kb * 2 + tg * 4;
                const char* pl = sAl + (mwarp + mt * 16 + g) * SAB + kb * 2 + tg * 4;
                Ah[mt][0] = *(const uint32_t*)(pa);
                Ah[mt][1] = *(const uint32_t*)(pa + 8 * SAB);
                Ah[mt][2] = *(const uint32_t*)(pa + 16);
                Ah[mt][3] = *(const uint32_t*)(pa + 8 * SAB + 16);
                Al[mt][0] = *(const uint32_t*)(pl);
                Al[mt][1] = *(const uint32_t*)(pl + 8 * SAB);
                Al[mt][2] = *(const uint32_t*)(pl + 16);
                Al[mt][3] = *(const uint32_t*)(pl + 8 * SAB + 16);
            }
            uint32_t Bh[NT][2], Bl[NT][2];
#pragma unroll
            for (int nt = 0; nt < NT; nt++) {
                const char* pb = sBh + (nwarp + nt * 8 + g) * SAB + kb * 2 + tg * 4;
                const char* pq = sBl + (nwarp + nt * 8 + g) * SAB + kb * 2 + tg * 4;
                Bh[nt][0] = *(const uint32_t*)(pb);
                Bh[nt][1] = *(const uint32_t*)(pb + 16);
                Bl[nt][0] = *(const uint32_t*)(pq);
                Bl[nt][1] = *(const uint32_t*)(pq + 16);
            }
#pragma unroll
            for (int mt = 0; mt < 2; mt++)
#pragma unroll
                for (int nt = 0; nt < NT; nt++) {
                    mma_bf16(C[mt][nt], Ah[mt][0], Ah[mt][1], Ah[mt][2], Ah[mt][3],
                             Bh[nt][0], Bh[nt][1]);
                    mma_bf16(C[mt][nt], Al[mt][0], Al[mt][1], Al[mt][2], Al[mt][3],
                             Bh[nt][0], Bh[nt][1]);
                    mma_bf16(C[mt][nt], Ah[mt][0], Ah[mt][1], Ah[mt][2], Ah[mt][3],
                             Bl[nt][0], Bl[nt][1]);
                }
        }
        __syncthreads();

#pragma unroll
        for (int mt = 0; mt < 2; mt++) {
            int rowA = r0 + mwarp + mt * 16 + g;
            int rowB = rowA + 8;
#pragma unroll
            for (int nt = 0; nt < NT; nt++) {
                int lcol = nwarp + nt * 8 + tg * 2;
                int col = coloff + lcol;
                float bx = sbias[lcol], by = sbias[lcol + 1];
                if (rowA < NN) {
                    float2 o;
                    o.x = C[mt][nt][0] + bx;
                    o.y = C[mt][nt][1] + by;
                    if (RELU) { o.x = fmaxf(o.x, 0.f); o.y = fmaxf(o.y, 0.f); }
                    *reinterpret_cast<float2*>(&out[(size_t)rowA * NOUT + col]) = o;
                    if (WRITEH) {
                        __half2 h = __floats2half2_rn(o.x, o.y);
                        *reinterpret_cast<__half2*>(&outh[(size_t)rowA * NOUT + col]) = h;
                    }
                }
                if (rowB < NN) {
                    float2 o;
                    o.x = C[mt][nt][2] + bx;
                    o.y = C[mt][nt][3] + by;
                    if (RELU) { o.x = fmaxf(o.x, 0.f); o.y = fmaxf(o.y, 0.f); }
                    *reinterpret_cast<float2*>(&out[(size_t)rowB * NOUT + col]) = o;
                    if (WRITEH) {
                        __half2 h = __floats2half2_rn(o.x, o.y);
                        *reinterpret_cast<__half2*>(&outh[(size_t)rowB * NOUT + col]) = h;
                    }
                }
            }
        }
    }
}

// ==================== layer 3 ====================
__global__ void k_l3a(const float* __restrict__ W4l, const float* __restrict__ b4,
                      const float* __restrict__ W4r, float* __restrict__ out) {
    __shared__ float swl[384], swr[384], sb3[3];
    int tid = threadIdx.x;
    for (int i = tid; i < 384; i += blockDim.x) { swl[i] = W4l[i]; swr[i] = W4r[i]; }
    if (tid < 3) sb3[tid] = b4[tid];
    __syncthreads();
    int r = blockIdx.x * blockDim.x + tid;
    if (r >= NN) return;
    const float4* h = reinterpret_cast<const float4*>(g_h2 + (size_t)r * 128);
    float l[3] = {0.f, 0.f, 0.f};
    float rr[3] = {0.f, 0.f, 0.f};
#pragma unroll
    for (int k4 = 0; k4 < 32; k4++) {
        float4 v = h[k4];
        float vv[4] = {v.x, v.y, v.z, v.w};
#pragma unroll
        for (int q = 0; q < 4; q++) {
            int k = k4 * 4 + q;
#pragma unroll
            for (int m = 0; m < 3; m++) {
                l[m] += vv[q] * swl[m * 128 + k];
                rr[m] += vv[q] * swr[m * 128 + k];
            }
        }
    }
    reinterpret_cast<float4*>(g_z)[r] = make_float4(l[0], l[1], l[2], 0.f);
#pragma unroll
    for (int m = 0; m < 3; m++) out[(size_t)r * 3 + m] = rr[m] + sb3[m];
}

__global__ void k_gather3(float* __restrict__ out) {
    int n = blockIdx.x * blockDim.x + threadIdx.x;
    if (n >= NN) return;
    int beg = g_rowptr[n], end = g_rowptr[n + 1];
    const float4* z4 = reinterpret_cast<const float4*>(g_z);
    float4 a0 = make_float4(0.f, 0.f, 0.f, 0.f), a1 = a0;
    int i = beg;
    for (; i + 2 <= end; i += 2) {
        float4 v0 = z4[g_csr[i]];
        float4 v1 = z4[g_csr[i + 1]];
        a0.x += v0.x; a0.y += v0.y; a0.z += v0.z;
        a1.x += v1.x; a1.y += v1.y; a1.z += v1.z;
    }
    if (i < end) {
        float4 v = z4[g_csr[i]];
        a0.x += v.x; a0.y += v.y; a0.z += v.z;
    }
    float di = g_dinv[n];
    out[(size_t)n * 3 + 0] += (a0.x + a1.x) * di;
    out[(size_t)n * 3 + 1] += (a0.y + a1.y) * di;
    out[(size_t)n * 3 + 2] += (a0.z + a1.z) * di;
}

// ==================== launch ====================
extern "C" void kernel_launch(void* const* d_in, const int* in_sizes, int n_in,
                              void* d_out, int out_size) {
    (void)in_sizes; (void)n_in; (void)out_size;
    const float* x   = (const float*)d_in[0];
    const int*   ei  = (const int*)d_in[1];
    const float* W1l = (const float*)d_in[2];
    const float* b1  = (const float*)d_in[3];
    const float* W1r = (const float*)d_in[4];
    const float* W2l = (const float*)d_in[5];
    const float* b2  = (const float*)d_in[6];
    const float* W2r = (const float*)d_in[7];
    const float* W4l = (const float*)d_in[8];
    const float* b4  = (const float*)d_in[9];
    const float* W4r = (const float*)d_in[10];
    float* out = (float*)d_out;

    void *p_agg1, *p_agg2, *p_h1, *p_h2, *p_xh, *p_h1h;
    cudaGetSymbolAddress(&p_agg1, g_agg1);
    cudaGetSymbolAddress(&p_agg2, g_agg2);
    cudaGetSymbolAddress(&p_h1, g_h1);
    cudaGetSymbolAddress(&p_h2, g_h2);
    cudaGetSymbolAddress(&p_xh, g_xh);
    cudaGetSymbolAddress(&p_h1h, g_h1h);

    int smem1 = 512 + 2 * 128 * (88 * 2) + 2 * 64 * (88 * 2);     // 68096  -> 3 blocks/SM
    int smem2 = 512 + 2 * 128 * (136 * 2) + 2 * 64 * (136 * 2);   // 104960 -> 2 blocks/SM
    cudaFuncSetAttribute((const void*)k_layer_mma<40, 64, true, true>,
                         cudaFuncAttributeMaxDynamicSharedMemorySize, smem1);
    cudaFuncSetAttribute((const void*)k_layer_mma<64, 64, true, false>,
                         cudaFuncAttributeMaxDynamicSharedMemorySize, smem2);

    // CSR build (+ x fp16 mirror, independent)
    k_zero0<<<(NN + 255) / 256, 256>>>();
    k_xhalf<<<(NN * 10 + 255) / 256, 256>>>(x);
    k_edges<<<(NE + 255) / 256, 256>>>(ei);
    k_scan1<<<SCAN_NB, SCAN_B>>>();
    k_scanf<<<(NN + 255) / 256, 256>>>();
    k_fill<<<(NE + 255) / 256, 256>>>();

    // layer 1: gather x (fp16 payload), fused linear -> h1 fp32 + fp16 mirror
    k_gather_h<10><<<(NN * 10 + 255) / 256, 256>>>((const __half*)p_xh, (float*)p_agg1);
    k_layer_mma<40, 64, true, true><<<dim3(3 * NSM, 1), 256, smem1>>>(
        x, (const float*)p_agg1, W1l, b1, W1r, (float*)p_h1, (__half*)p_h1h, 64);

    // layer 2: gather h1 (fp16 payload), fused linear -> h2 [N,128]
    k_gather_h<16><<<(NN * 16 + 255) / 256, 256>>>((const __half*)p_h1h, (float*)p_agg2);
    k_layer_mma<64, 64, true, false><<<dim3(NSM, 2), 256, smem2>>>(
        (const float*)p_h1, (const float*)p_agg2, W2l, b2, W2r, (float*)p_h2,
        (__half*)nullptr, 128);

    // layer 3: transform FIRST (3 outputs), aggregate 4 floats/edge
    k_l3a<<<(NN + 127) / 128, 128>>>(W4l, b4, W4r, out);
    k_gather3<<<(NN + 255) / 256, 256>>>(out);
}

// round 7
// speedup vs baseline: 1.0352x; 1.0352x over previous
#include <cuda_runtime.h>
#include <cuda_bf16.h>
#include <cuda_fp16.h>
#include <cstdint>
#include <cstddef>
#include <cstring>

#define NN 100000
#define NE 1600000
#define SCAN_B 512
#define SCAN_NB ((NN + SCAN_B - 1) / SCAN_B)   // 196
#define NSM 152

// ---------------- scratch (static device globals; no allocs allowed) ----------------
__device__ int   g_degi[NN];
__device__ float g_dinv[NN];
__device__ int   g_src[NE];
__device__ int   g_dst[NE];
__device__ int   g_csr[NE];
__device__ int   g_rowptr[NN + 1];
__device__ int   g_cursor[NN];
__device__ int   g_bsum[256];
__device__ __align__(16) float  g_agg1[(size_t)NN * 40];
__device__ __align__(16) float  g_h1[(size_t)NN * 64];
__device__ __align__(16) __half g_xh[(size_t)NN * 40];
__device__ __align__(16) __half g_h1h[(size_t)NN * 64];
__device__ __align__(16) float  g_agg2[(size_t)NN * 64];
__device__ __align__(16) float  g_h2[(size_t)NN * 128];
__device__ __align__(16) float  g_z[(size_t)NN * 4];

// ==================== CSR build ====================
__global__ void k_zero0() {
    int i = blockIdx.x * blockDim.x + threadIdx.x;
    if (i < NN) g_degi[i] = 0;
}

__global__ void k_edges(const int* __restrict__ ei32) {
    bool is64 = true;
#pragma unroll
    for (int q = 1; q < 16; q += 2) is64 = is64 && (ei32[q] == 0);
    int e = blockIdx.x * blockDim.x + threadIdx.x;
    if (e >= NE) return;
    int s, d;
    if (is64) { s = ei32[2 * e];  d = ei32[2 * (NE + e)]; }
    else      { s = ei32[e];      d = ei32[NE + e]; }
    g_src[e] = s;
    g_dst[e] = d;
    atomicAdd(&g_degi[d], 1);
}

// block-local inclusive scan + per-block sum + dinv
__global__ void k_scan1() {
    __shared__ int sh[SCAN_B];
    int i = blockIdx.x * SCAN_B + threadIdx.x;
    int v = (i < NN) ? g_degi[i] : 0;
    sh[threadIdx.x] = v;
    __syncthreads();
    for (int off = 1; off < SCAN_B; off <<= 1) {
        int t = (threadIdx.x >= off) ? sh[threadIdx.x - off] : 0;
        __syncthreads();
        sh[threadIdx.x] += t;
        __syncthreads();
    }
    if (i < NN) {
        g_rowptr[i] = sh[threadIdx.x] - v;  // block-local exclusive
        g_dinv[i] = (v > 0) ? (1.f / (float)v) : 0.f;
    }
    if (threadIdx.x == SCAN_B - 1) g_bsum[blockIdx.x] = sh[threadIdx.x];
}

// finalize rowptr/cursor; nb constant per block -> parallel reduction over g_bsum
__global__ void k_scanf() {
    __shared__ int ssum[8];
    int tid = threadIdx.x;
    int nb = (blockIdx.x * 256) / SCAN_B;
    int part = 0;
    for (int b = tid; b < nb; b += 256) part += g_bsum[b];
#pragma unroll
    for (int o = 16; o; o >>= 1) part += __shfl_down_sync(0xFFFFFFFFu, part, o);
    if ((tid & 31) == 0) ssum[tid >> 5] = part;
    __syncthreads();
    int off = ssum[0] + ssum[1] + ssum[2] + ssum[3]
            + ssum[4] + ssum[5] + ssum[6] + ssum[7];
    int i = blockIdx.x * 256 + tid;
    if (i >= NN) return;
    int rp = g_rowptr[i] + off;
    g_rowptr[i] = rp;
    g_cursor[i] = rp;
    if (i == 0) g_rowptr[NN] = NE;
}

__global__ void k_fill() {
    int e = blockIdx.x * blockDim.x + threadIdx.x;
    if (e >= NE) return;
    int pos = atomicAdd(&g_cursor[g_dst[e]], 1);
    g_csr[pos] = g_src[e];
}

// ==================== x -> fp16 mirror ====================
__global__ void k_xhalf(const float* __restrict__ x) {
    int t = blockIdx.x * blockDim.x + threadIdx.x;  // one float4 -> 4 halves
    if (t >= NN * 10) return;
    float4 v = reinterpret_cast<const float4*>(x)[t];
    __half2 a = __floats2half2_rn(v.x, v.y);
    __half2 b = __floats2half2_rn(v.z, v.w);
    uint32_t ua, ub;
    memcpy(&ua, &a, 4);
    memcpy(&ub, &b, 4);
    reinterpret_cast<uint2*>(g_xh)[t] = make_uint2(ua, ub);
}

// by-value u32 -> float2 (memcpy punning; no address-of-register hazards)
__device__ __forceinline__ float2 h2f(uint32_t u) {
    __half2 h;
    memcpy(&h, &u, 4);
    return __half22float2(h);
}

// ==================== CSR gather (fp16, WIDE): agg[n]=dinv*sum feat[nbrs] ====================
// FC4 chunks of uint4 (8 halves = 16B) per row -> half the threads & warp-LDGs of fp32 ver.
template <int FC4>
__global__ void __launch_bounds__(256) k_gather_hw(const __half* __restrict__ feat,
                                                   float* __restrict__ agg) {
    int t = blockIdx.x * blockDim.x + threadIdx.x;
    if (t >= NN * FC4) return;
    int n = t / FC4;
    int c = t - n * FC4;
    int beg = g_rowptr[n], end = g_rowptr[n + 1];
    const uint4* f = reinterpret_cast<const uint4*>(feat);
    float a0[8] = {0.f, 0.f, 0.f, 0.f, 0.f, 0.f, 0.f, 0.f};
    float a1[8] = {0.f, 0.f, 0.f, 0.f, 0.f, 0.f, 0.f, 0.f};
    int i = beg;
    for (; i + 2 <= end; i += 2) {
        int s0 = g_csr[i], s1 = g_csr[i + 1];
        uint4 u0 = f[(size_t)s0 * FC4 + c];
        uint4 u1 = f[(size_t)s1 * FC4 + c];
        float2 p;
        p = h2f(u0.x); a0[0] += p.x; a0[1] += p.y;
        p = h2f(u0.y); a0[2] += p.x; a0[3] += p.y;
        p = h2f(u0.z); a0[4] += p.x; a0[5] += p.y;
        p = h2f(u0.w); a0[6] += p.x; a0[7] += p.y;
        p = h2f(u1.x); a1[0] += p.x; a1[1] += p.y;
        p = h2f(u1.y); a1[2] += p.x; a1[3] += p.y;
        p = h2f(u1.z); a1[4] += p.x; a1[5] += p.y;
        p = h2f(u1.w); a1[6] += p.x; a1[7] += p.y;
    }
    if (i < end) {
        uint4 u = f[(size_t)g_csr[i] * FC4 + c];
        float2 p;
        p = h2f(u.x); a0[0] += p.x; a0[1] += p.y;
        p = h2f(u.y); a0[2] += p.x; a0[3] += p.y;
        p = h2f(u.z); a0[4] += p.x; a0[5] += p.y;
        p = h2f(u.w); a0[6] += p.x; a0[7] += p.y;
    }
    float di = g_dinv[n];
    float* dst = agg + (size_t)n * (FC4 * 8) + c * 8;
    float4 o0, o1;
    o0.x = (a0[0] + a1[0]) * di; o0.y = (a0[1] + a1[1]) * di;
    o0.z = (a0[2] + a1[2]) * di; o0.w = (a0[3] + a1[3]) * di;
    o1.x = (a0[4] + a1[4]) * di; o1.y = (a0[5] + a1[5]) * di;
    o1.z = (a0[6] + a1[6]) * di; o1.w = (a0[7] + a1[7]) * di;
    *reinterpret_cast<float4*>(dst) = o0;
    *reinterpret_cast<float4*>(dst + 4) = o1;
}

// ==================== HMMA helpers ====================
__device__ __forceinline__ void mma_bf16(float* c, uint32_t a0, uint32_t a1,
                                         uint32_t a2, uint32_t a3,
                                         uint32_t b0, uint32_t b1) {
    asm volatile(
        "mma.sync.aligned.m16n8k16.row.col.f32.bf16.bf16.f32 "
        "{%0,%1,%2,%3}, {%4,%5,%6,%7}, {%8,%9}, {%0,%1,%2,%3};"
        : "+f"(c[0]), "+f"(c[1]), "+f"(c[2]), "+f"(c[3])
        : "r"(a0), "r"(a1), "r"(a2), "r"(a3), "r"(b0), "r"(b1));
}

__device__ __forceinline__ uint32_t pack_bf(float a, float b) {
    __nv_bfloat162 t = __floats2bfloat162_rn(a, b);
    uint32_t u;
    memcpy(&u, &t, 4);
    return u;
}

__device__ __forceinline__ void store_hilo(char* pHi, char* pLo, float4 v) {
    float hx = __bfloat162float(__float2bfloat16_rn(v.x));
    float hy = __bfloat162float(__float2bfloat16_rn(v.y));
    float hz = __bfloat162float(__float2bfloat16_rn(v.z));
    float hw = __bfloat162float(__float2bfloat16_rn(v.w));
    *reinterpret_cast<uint2*>(pHi) = make_uint2(pack_bf(hx, hy), pack_bf(hz, hw));
    *reinterpret_cast<uint2*>(pLo) =
        make_uint2(pack_bf(v.x - hx, v.y - hy), pack_bf(v.z - hz, v.w - hw));
}

// ==================== fused SAGE layer via mma.sync (bf16 hi/lo split) ====================
template <int K, int NOUTB, bool RELU, bool WRITEH>
__global__ void __launch_bounds__(256) k_layer_mma(
        const float* __restrict__ in, const float* __restrict__ agg,
        const float* __restrict__ Wl, const float* __restrict__ bias,
        const float* __restrict__ Wr, float* __restrict__ out,
        __half* __restrict__ outh, int NOUT) {
    constexpr int Kc = 2 * K;
    constexpr int KSTEPS = Kc / 16;
    constexpr int K4 = Kc / 4;
    constexpr int SA = Kc + 8;           // +16B row pad: conflict-free frag loads
    constexpr int SAB = SA * 2;
    constexpr int NT = (NOUTB / 2) / 8;
    constexpr int NTILES = (NN + 127) / 128;
    constexpr int OFF_AH = 512;
    constexpr int OFF_AL = OFF_AH + 128 * SAB;
    constexpr int OFF_BH = OFF_AL + 128 * SAB;
    constexpr int OFF_BL = OFF_BH + NOUTB * SAB;

    extern __shared__ char smem[];
    float* sbias = reinterpret_cast<float*>(smem);
    char* sAh = smem + OFF_AH;
    char* sAl = smem + OFF_AL;
    char* sBh = smem + OFF_BH;
    char* sBl = smem + OFF_BL;

    int tid = threadIdx.x;
    int wid = tid >> 5, lane = tid & 31;
    int g = lane >> 2, tg = lane & 3;
    int mwarp = (wid & 3) * 32;
    int nwarp = (wid >> 2) * (NOUTB / 2);
    int coloff = blockIdx.y * NOUTB;

    if (tid < NOUTB) sbias[tid] = bias[coloff + tid];
    for (int idx = tid; idx < NOUTB * K4; idx += 256) {
        int row = idx / K4, k4 = idx - row * K4;
        int k = k4 * 4;
        int grow = coloff + row;
        float4 v = (k < K)
            ? *reinterpret_cast<const float4*>(Wl + (size_t)grow * K + k)
            : *reinterpret_cast<const float4*>(Wr + (size_t)grow * K + (k - K));
        store_hilo(sBh + row * SAB + k * 2, sBl + row * SAB + k * 2, v);
    }
    __syncthreads();

    for (int tile = blockIdx.x; tile < NTILES; tile += gridDim.x) {
        int r0 = tile * 128;
        for (int idx = tid; idx < 128 * K4; idx += 256) {
            int row = idx / K4, k4 = idx - row * K4;
            int k = k4 * 4;
            int gr = r0 + row;
            float4 v = make_float4(0.f, 0.f, 0.f, 0.f);
            if (gr < NN) {
                v = (k < K)
                    ? *reinterpret_cast<const float4*>(agg + (size_t)gr * K + k)
                    : *reinterpret_cast<const float4*>(in + (size_t)gr * K + (k - K));
            }
            store_hilo(sAh + row * SAB + k * 2, sAl + row * SAB + k * 2, v);
        }
        __syncthreads();

        float C[2][NT][4];
#pragma unroll
        for (int mt = 0; mt < 2; mt++)
#pragma unroll
            for (int nt = 0; nt < NT; nt++)
#pragma unroll
                for (int q = 0; q < 4; q++) C[mt][nt][q] = 0.f;

#pragma unroll
        for (int ks = 0; ks < KSTEPS; ks++) {
            int kb = ks * 16;
            uint32_t Ah[2][4], Al[2][4];
#pragma unroll
            for (int mt = 0; mt < 2; mt++) {
                const char* pa = sAh + (mwarp + mt * 16 + g) * SAB + kb * 2 + tg * 4;
                const char* pl = sAl + (mwarp + mt * 16 + g) * SAB + kb * 2 + tg * 4;
                Ah[mt][0] = *(const uint32_t*)(pa);
                Ah[mt][1] = *(const uint32_t*)(pa + 8 * SAB);
                Ah[mt][2] = *(const uint32_t*)(pa + 16);
                Ah[mt][3] = *(const uint32_t*)(pa + 8 * SAB + 16);
                Al[mt][0] = *(const uint32_t*)(pl);
                Al[mt][1] = *(const uint32_t*)(pl + 8 * SAB);
                Al[mt][2] = *(const uint32_t*)(pl + 16);
                Al[mt][3] = *(const uint32_t*)(pl + 8 * SAB + 16);
            }
            uint32_t Bh[NT][2], Bl[NT][2];
#pragma unroll
            for (int nt = 0; nt < NT; nt++) {
                const char* pb = sBh + (nwarp + nt * 8 + g) * SAB + kb * 2 + tg * 4;
                const char* pq = sBl + (nwarp + nt * 8 + g) * SAB + kb * 2 + tg * 4;
                Bh[nt][0] = *(const uint32_t*)(pb);
                Bh[nt][1] = *(const uint32_t*)(pb + 16);
                Bl[nt][0] = *(const uint32_t*)(pq);
                Bl[nt][1] = *(const uint32_t*)(pq + 16);
            }
#pragma unroll
            for (int mt = 0; mt < 2; mt++)
#pragma unroll
                for (int nt = 0; nt < NT; nt++) {
                    mma_bf16(C[mt][nt], Ah[mt][0], Ah[mt][1], Ah[mt][2], Ah[mt][3],
                             Bh[nt][0], Bh[nt][1]);
                    mma_bf16(C[mt][nt], Al[mt][0], Al[mt][1], Al[mt][2], Al[mt][3],
                             Bh[nt][0], Bh[nt][1]);
                    mma_bf16(C[mt][nt], Ah[mt][0], Ah[mt][1], Ah[mt][2], Ah[mt][3],
                             Bl[nt][0], Bl[nt][1]);
                }
        }
        __syncthreads();

#pragma unroll
        for (int mt = 0; mt < 2; mt++) {
            int rowA = r0 + mwarp + mt * 16 + g;
            int rowB = rowA + 8;
#pragma unroll
            for (int nt = 0; nt < NT; nt++) {
                int lcol = nwarp + nt * 8 + tg * 2;
                int col = coloff + lcol;
                float bx = sbias[lcol], by = sbias[lcol + 1];
                if (rowA < NN) {
                    float2 o;
                    o.x = C[mt][nt][0] + bx;
                    o.y = C[mt][nt][1] + by;
                    if (RELU) { o.x = fmaxf(o.x, 0.f); o.y = fmaxf(o.y, 0.f); }
                    *reinterpret_cast<float2*>(&out[(size_t)rowA * NOUT + col]) = o;
                    if (WRITEH) {
                        __half2 h = __floats2half2_rn(o.x, o.y);
                        *reinterpret_cast<__half2*>(&outh[(size_t)rowA * NOUT + col]) = h;
                    }
                }
                if (rowB < NN) {
                    float2 o;
                    o.x = C[mt][nt][2] + bx;
                    o.y = C[mt][nt][3] + by;
                    if (RELU) { o.x = fmaxf(o.x, 0.f); o.y = fmaxf(o.y, 0.f); }
                    *reinterpret_cast<float2*>(&out[(size_t)rowB * NOUT + col]) = o;
                    if (WRITEH) {
                        __half2 h = __floats2half2_rn(o.x, o.y);
                        *reinterpret_cast<__half2*>(&outh[(size_t)rowB * NOUT + col]) = h;
                    }
                }
            }
        }
    }
}

// ==================== layer 3 ====================
__global__ void k_l3a(const float* __restrict__ W4l, const float* __restrict__ b4,
                      const float* __restrict__ W4r, float* __restrict__ out) {
    __shared__ float swl[384], swr[384], sb3[3];
    int tid = threadIdx.x;
    for (int i = tid; i < 384; i += blockDim.x) { swl[i] = W4l[i]; swr[i] = W4r[i]; }
    if (tid < 3) sb3[tid] = b4[tid];
    __syncthreads();
    int r = blockIdx.x * blockDim.x + tid;
    if (r >= NN) return;
    const float4* h = reinterpret_cast<const float4*>(g_h2 + (size_t)r * 128);
    float l[3] = {0.f, 0.f, 0.f};
    float rr[3] = {0.f, 0.f, 0.f};
#pragma unroll
    for (int k4 = 0; k4 < 32; k4++) {
        float4 v = h[k4];
        float vv[4] = {v.x, v.y, v.z, v.w};
#pragma unroll
        for (int q = 0; q < 4; q++) {
            int k = k4 * 4 + q;
#pragma unroll
            for (int m = 0; m < 3; m++) {
                l[m] += vv[q] * swl[m * 128 + k];
                rr[m] += vv[q] * swr[m * 128 + k];
            }
        }
    }
    reinterpret_cast<float4*>(g_z)[r] = make_float4(l[0], l[1], l[2], 0.f);
#pragma unroll
    for (int m = 0; m < 3; m++) out[(size_t)r * 3 + m] = rr[m] + sb3[m];
}

__global__ void k_gather3(float* __restrict__ out) {
    int n = blockIdx.x * blockDim.x + threadIdx.x;
    if (n >= NN) return;
    int beg = g_rowptr[n], end = g_rowptr[n + 1];
    const float4* z4 = reinterpret_cast<const float4*>(g_z);
    float4 a0 = make_float4(0.f, 0.f, 0.f, 0.f), a1 = a0;
    int i = beg;
    for (; i + 2 <= end; i += 2) {
        float4 v0 = z4[g_csr[i]];
        float4 v1 = z4[g_csr[i + 1]];
        a0.x += v0.x; a0.y += v0.y; a0.z += v0.z;
        a1.x += v1.x; a1.y += v1.y; a1.z += v1.z;
    }
    if (i < end) {
        float4 v = z4[g_csr[i]];
        a0.x += v.x; a0.y += v.y; a0.z += v.z;
    }
    float di = g_dinv[n];
    out[(size_t)n * 3 + 0] += (a0.x + a1.x) * di;
    out[(size_t)n * 3 + 1] += (a0.y + a1.y) * di;
    out[(size_t)n * 3 + 2] += (a0.z + a1.z) * di;
}

// ==================== launch ====================
extern "C" void kernel_launch(void* const* d_in, const int* in_sizes, int n_in,
                              void* d_out, int out_size) {
    (void)in_sizes; (void)n_in; (void)out_size;
    const float* x   = (const float*)d_in[0];
    const int*   ei  = (const int*)d_in[1];
    const float* W1l = (const float*)d_in[2];
    const float* b1  = (const float*)d_in[3];
    const float* W1r = (const float*)d_in[4];
    const float* W2l = (const float*)d_in[5];
    const float* b2  = (const float*)d_in[6];
    const float* W2r = (const float*)d_in[7];
    const float* W4l = (const float*)d_in[8];
    const float* b4  = (const float*)d_in[9];
    const float* W4r = (const float*)d_in[10];
    float* out = (float*)d_out;

    void *p_agg1, *p_agg2, *p_h1, *p_h2, *p_xh, *p_h1h;
    cudaGetSymbolAddress(&p_agg1, g_agg1);
    cudaGetSymbolAddress(&p_agg2, g_agg2);
    cudaGetSymbolAddress(&p_h1, g_h1);
    cudaGetSymbolAddress(&p_h2, g_h2);
    cudaGetSymbolAddress(&p_xh, g_xh);
    cudaGetSymbolAddress(&p_h1h, g_h1h);

    int smem1 = 512 + 2 * 128 * (88 * 2) + 2 * 64 * (88 * 2);     // 68096  -> 3 blocks/SM
    int smem2 = 512 + 2 * 128 * (136 * 2) + 2 * 64 * (136 * 2);   // 104960 -> 2 blocks/SM
    cudaFuncSetAttribute((const void*)k_layer_mma<40, 64, true, true>,
                         cudaFuncAttributeMaxDynamicSharedMemorySize, smem1);
    cudaFuncSetAttribute((const void*)k_layer_mma<64, 64, true, false>,
                         cudaFuncAttributeMaxDynamicSharedMemorySize, smem2);

    // CSR build (+ x fp16 mirror, independent)
    k_zero0<<<(NN + 255) / 256, 256>>>();
    k_xhalf<<<(NN * 10 + 255) / 256, 256>>>(x);
    k_edges<<<(NE + 255) / 256, 256>>>(ei);
    k_scan1<<<SCAN_NB, SCAN_B>>>();
    k_scanf<<<(NN + 255) / 256, 256>>>();
    k_fill<<<(NE + 255) / 256, 256>>>();

    // layer 1: gather x (fp16, wide 16B loads, FC4=5), fused linear -> h1 + fp16 mirror
    k_gather_hw<5><<<(NN * 5 + 255) / 256, 256>>>((const __half*)p_xh, (float*)p_agg1);
    k_layer_mma<40, 64, true, true><<<dim3(3 * NSM, 1), 256, smem1>>>(
        x, (const float*)p_agg1, W1l, b1, W1r, (float*)p_h1, (__half*)p_h1h, 64);

    // layer 2: gather h1 (fp16, wide, FC4=8), fused linear -> h2 [N,128]
    k_gather_hw<8><<<(NN * 8 + 255) / 256, 256>>>((const __half*)p_h1h, (float*)p_agg2);
    k_layer_mma<64, 64, true, false><<<dim3(NSM, 2), 256, smem2>>>(
        (const float*)p_h1, (const float*)p_agg2, W2l, b2, W2r, (float*)p_h2,
        (__half*)nullptr, 128);

    // layer 3: transform FIRST (3 outputs), aggregate 4 floats/edge
    k_l3a<<<(NN + 127) / 128, 128>>>(W4l, b4, W4r, out);
    k_gather3<<<(NN + 255) / 256, 256>>>(out);
}